// round 1
// baseline (speedup 1.0000x reference)
#include <cuda_runtime.h>

#define NB_T 34
#define NB_S 16
#define NTHREADS 544   // NB_T * NB_S
#define KV_STRIDE 548  // floats per sequence in kv buffer (34*16 + 4 pad -> conflict-free)

__device__ __forceinline__ float ex2(float x) { float y; asm("ex2.approx.ftz.f32 %0, %1;" : "=f"(y) : "f"(x)); return y; }
__device__ __forceinline__ float rsq(float x) { float y; asm("rsqrt.approx.f32 %0, %1;" : "=f"(y) : "f"(x)); return y; }
__device__ __forceinline__ float rcp(float x) { float y; asm("rcp.approx.f32 %0, %1;" : "=f"(y) : "f"(x)); return y; }

// shared weight-buffer offsets (floats)
#define W_TOK   0     // 14*3 = 42
#define W_POS   42    // 34*3 = 102
#define W_LNW   144   // 4*6  = 24
#define W_LNB   168   // 24
#define W_Q1    192   // 4*9 = 36
#define W_K1    228
#define W_V1    264
#define W_Q2    300
#define W_K2    336
#define W_V2    372
#define W_OUT   408   // 4*36 = 144
#define W_LNF   552   // 6
#define W_LNFB  558   // 6
#define W_HEAD  564   // 14*6 = 84
#define W_TOTAL 648

__global__ __launch_bounds__(NTHREADS, 2)
void addtrans_kernel(const int* __restrict__ gidx,
                     const float* __restrict__ tok_emb, const float* __restrict__ pos_enc,
                     const float* __restrict__ ln_w,   const float* __restrict__ ln_b,
                     const float* __restrict__ q1w,    const float* __restrict__ k1w, const float* __restrict__ v1w,
                     const float* __restrict__ q2w,    const float* __restrict__ k2w, const float* __restrict__ v2w,
                     const float* __restrict__ out_w,
                     const float* __restrict__ lnf_w,  const float* __restrict__ lnf_b,
                     const float* __restrict__ head_w,
                     float* __restrict__ out)
{
    __shared__ __align__(16) float skv[NB_S * KV_STRIDE];
    __shared__ float sw[W_TOTAL];
    __shared__ int   sidx[NTHREADS];

    const int tid = threadIdx.x;

    // ---- stage weights into shared (broadcast-friendly thereafter) ----
    if (tid < 42)  sw[W_TOK  + tid] = tok_emb[tid];
    if (tid < 102) sw[W_POS  + tid] = pos_enc[tid];
    if (tid < 24)  { sw[W_LNW + tid] = ln_w[tid]; sw[W_LNB + tid] = ln_b[tid]; }
    if (tid < 36)  {
        sw[W_Q1 + tid] = q1w[tid]; sw[W_K1 + tid] = k1w[tid]; sw[W_V1 + tid] = v1w[tid];
        sw[W_Q2 + tid] = q2w[tid]; sw[W_K2 + tid] = k2w[tid]; sw[W_V2 + tid] = v2w[tid];
    }
    if (tid < 144) sw[W_OUT + tid] = out_w[tid];
    if (tid < 6)   { sw[W_LNF + tid] = lnf_w[tid]; sw[W_LNFB + tid] = lnf_b[tid]; }
    if (tid < 84)  sw[W_HEAD + tid] = head_w[tid];
    // stage idx coalesced: block covers 544 contiguous int32 of idx
    sidx[tid] = gidx[(size_t)blockIdx.x * NTHREADS + tid];
    __syncthreads();

    // token-major layout: lanes of a warp cover 2 adjacent tokens x 16 seqs
    const int t  = tid / NB_S;      // token 0..33
    const int sl = tid % NB_S;      // local sequence 0..15
    const int token = sidx[sl * NB_T + t];

    // residual stream
    float x0 = sw[W_TOK + token*3 + 0];
    float x1 = sw[W_TOK + token*3 + 1];
    float x2 = sw[W_TOK + token*3 + 2];
    float x3 = sw[W_POS + t*3 + 0];
    float x4 = sw[W_POS + t*3 + 1];
    float x5 = sw[W_POS + t*3 + 2];

    float* mykv = &skv[sl * KV_STRIDE + t * 16];
    const float4* kbase = (const float4*)&skv[sl * KV_STRIDE];

    // fold 1/sqrt(3) (attention scale) and log2(e) (for ex2) into q
    const float QSCALE = 0.57735026919f * 1.44269504089f;

    #pragma unroll
    for (int l = 0; l < 4; ++l) {
        // ---- layernorm ----
        float m = (x0 + x1 + x2 + x3 + x4 + x5) * (1.0f / 6.0f);
        float d0 = x0 - m, d1 = x1 - m, d2 = x2 - m, d3 = x3 - m, d4 = x4 - m, d5 = x5 - m;
        float var = (d0*d0 + d1*d1 + d2*d2 + d3*d3 + d4*d4 + d5*d5) * (1.0f / 6.0f);
        float r = rsq(var + 1e-5f);
        const float* lw = &sw[W_LNW + l*6];
        const float* lb = &sw[W_LNB + l*6];
        float h0 = d0 * r * lw[0] + lb[0];
        float h1 = d1 * r * lw[1] + lb[1];
        float h2 = d2 * r * lw[2] + lb[2];
        float h3 = d3 * r * lw[3] + lb[3];
        float h4 = d4 * r * lw[4] + lb[4];
        float h5 = d5 * r * lw[5] + lb[5];

        // ---- projections (3x3) ----
        const float* w;
        w = &sw[W_Q1 + l*9];
        float q1x = (w[0]*h0 + w[1]*h1 + w[2]*h2) * QSCALE;
        float q1y = (w[3]*h0 + w[4]*h1 + w[5]*h2) * QSCALE;
        float q1z = (w[6]*h0 + w[7]*h1 + w[8]*h2) * QSCALE;
        w = &sw[W_K1 + l*9];
        float k1x = w[0]*h0 + w[1]*h1 + w[2]*h2;
        float k1y = w[3]*h0 + w[4]*h1 + w[5]*h2;
        float k1z = w[6]*h0 + w[7]*h1 + w[8]*h2;
        w = &sw[W_V1 + l*9];
        float v1x = w[0]*h0 + w[1]*h1 + w[2]*h2;
        float v1y = w[3]*h0 + w[4]*h1 + w[5]*h2;
        float v1z = w[6]*h0 + w[7]*h1 + w[8]*h2;
        w = &sw[W_Q2 + l*9];
        float q2x = (w[0]*h3 + w[1]*h4 + w[2]*h5) * QSCALE;
        float q2y = (w[3]*h3 + w[4]*h4 + w[5]*h5) * QSCALE;
        float q2z = (w[6]*h3 + w[7]*h4 + w[8]*h5) * QSCALE;
        w = &sw[W_K2 + l*9];
        float k2x = w[0]*h3 + w[1]*h4 + w[2]*h5;
        float k2y = w[3]*h3 + w[4]*h4 + w[5]*h5;
        float k2z = w[6]*h3 + w[7]*h4 + w[8]*h5;
        w = &sw[W_V2 + l*9];
        float v2x = w[0]*h3 + w[1]*h4 + w[2]*h5;
        float v2y = w[3]*h3 + w[4]*h4 + w[5]*h5;
        float v2z = w[6]*h3 + w[7]*h4 + w[8]*h5;

        // ---- publish k/v (3x STS.128, conflict-free) ----
        float4* kvp = (float4*)mykv;
        kvp[0] = make_float4(k1x, k1y, k1z, k2x);
        kvp[1] = make_float4(k2y, k2z, v1x, v1y);
        kvp[2] = make_float4(v1z, v2x, v2y, v2z);
        __syncthreads();

        // ---- causal attention, both heads, no-max softmax (scores bounded) ----
        float o1x = 0.f, o1y = 0.f, o1z = 0.f, den1 = 0.f;
        float o2x = 0.f, o2y = 0.f, o2z = 0.f, den2 = 0.f;
        for (int j = 0; j <= t; ++j) {
            float4 a = kbase[j*4 + 0];
            float4 b = kbase[j*4 + 1];
            float4 c = kbase[j*4 + 2];
            float s1 = q1x*a.x + q1y*a.y + q1z*a.z;
            float s2 = q2x*a.w + q2y*b.x + q2z*b.y;
            float p1 = ex2(s1);
            float p2 = ex2(s2);
            den1 += p1;
            den2 += p2;
            o1x += p1 * b.z;  o1y += p1 * b.w;  o1z += p1 * c.x;
            o2x += p2 * c.y;  o2y += p2 * c.z;  o2z += p2 * c.w;
        }
        float rd1 = rcp(den1);
        float rd2 = rcp(den2);
        float o0 = o1x*rd1, o1_ = o1y*rd1, o2_ = o1z*rd1;
        float o3 = o2x*rd2, o4 = o2y*rd2, o5 = o2z*rd2;

        // ---- output projection + residual ----
        const float* wo = &sw[W_OUT + l*36];
        x0 += wo[0]*o0  + wo[1]*o1_ + wo[2]*o2_ + wo[3]*o3  + wo[4]*o4  + wo[5]*o5;
        x1 += wo[6]*o0  + wo[7]*o1_ + wo[8]*o2_ + wo[9]*o3  + wo[10]*o4 + wo[11]*o5;
        x2 += wo[12]*o0 + wo[13]*o1_+ wo[14]*o2_+ wo[15]*o3 + wo[16]*o4 + wo[17]*o5;
        x3 += wo[18]*o0 + wo[19]*o1_+ wo[20]*o2_+ wo[21]*o3 + wo[22]*o4 + wo[23]*o5;
        x4 += wo[24]*o0 + wo[25]*o1_+ wo[26]*o2_+ wo[27]*o3 + wo[28]*o4 + wo[29]*o5;
        x5 += wo[30]*o0 + wo[31]*o1_+ wo[32]*o2_+ wo[33]*o3 + wo[34]*o4 + wo[35]*o5;

        __syncthreads();  // kv buffer reused next layer
    }

    // ---- final layernorm ----
    float m = (x0 + x1 + x2 + x3 + x4 + x5) * (1.0f / 6.0f);
    float d0 = x0 - m, d1 = x1 - m, d2 = x2 - m, d3 = x3 - m, d4 = x4 - m, d5 = x5 - m;
    float var = (d0*d0 + d1*d1 + d2*d2 + d3*d3 + d4*d4 + d5*d5) * (1.0f / 6.0f);
    float r = rsq(var + 1e-5f);
    float h0 = d0 * r * sw[W_LNF+0] + sw[W_LNFB+0];
    float h1 = d1 * r * sw[W_LNF+1] + sw[W_LNFB+1];
    float h2 = d2 * r * sw[W_LNF+2] + sw[W_LNFB+2];
    float h3 = d3 * r * sw[W_LNF+3] + sw[W_LNFB+3];
    float h4 = d4 * r * sw[W_LNF+4] + sw[W_LNFB+4];
    float h5 = d5 * r * sw[W_LNF+5] + sw[W_LNFB+5];

    // ---- head: 14 logits ----
    float lg[14];
    #pragma unroll
    for (int vtok = 0; vtok < 14; ++vtok) {
        const float* hw = &sw[W_HEAD + vtok*6];
        lg[vtok] = hw[0]*h0 + hw[1]*h1 + hw[2]*h2 + hw[3]*h3 + hw[4]*h4 + hw[5]*h5;
    }

    size_t base = ((size_t)(blockIdx.x * NB_S + sl) * NB_T + t) * 14;
    float2* op = (float2*)(out + base);   // 56B-aligned-to-8 ok
    #pragma unroll
    for (int i = 0; i < 7; ++i) op[i] = make_float2(lg[2*i], lg[2*i + 1]);
}

extern "C" void kernel_launch(void* const* d_in, const int* in_sizes, int n_in,
                              void* d_out, int out_size)
{
    (void)in_sizes; (void)n_in; (void)out_size;
    addtrans_kernel<<<1024, NTHREADS>>>(
        (const int*)d_in[0],
        (const float*)d_in[1],  (const float*)d_in[2],
        (const float*)d_in[3],  (const float*)d_in[4],
        (const float*)d_in[5],  (const float*)d_in[6],  (const float*)d_in[7],
        (const float*)d_in[8],  (const float*)d_in[9],  (const float*)d_in[10],
        (const float*)d_in[11],
        (const float*)d_in[12], (const float*)d_in[13],
        (const float*)d_in[14],
        (float*)d_out);
}

// round 4
// speedup vs baseline: 1.0486x; 1.0486x over previous
#include <cuda_runtime.h>

typedef unsigned long long ull;

#define NSEQ 8          // sequences per block
#define NTHREADS 288    // 9 warps: 8 full-token-group warps + 1 tail half-warp
#define SEQ_STRIDE 412  // floats per seq in kv (103 float4s; 103 mod 8 = 7 -> conflict-free)

__device__ __forceinline__ float ex2f(float x){ float y; asm("ex2.approx.ftz.f32 %0, %1;":"=f"(y):"f"(x)); return y; }
__device__ __forceinline__ float rsqf(float x){ float y; asm("rsqrt.approx.f32 %0, %1;":"=f"(y):"f"(x)); return y; }
__device__ __forceinline__ float rcpf(float x){ float y; asm("rcp.approx.f32 %0, %1;":"=f"(y):"f"(x)); return y; }
__device__ __forceinline__ ull pk(float lo, float hi){ ull r; asm("mov.b64 %0, {%1,%2};":"=l"(r):"f"(lo),"f"(hi)); return r; }
__device__ __forceinline__ void unpk(ull v, float&a, float&b){ asm("mov.b64 {%0,%1}, %2;":"=f"(a),"=f"(b):"l"(v)); }
__device__ __forceinline__ ull f2mul(ull a, ull b){ ull d; asm("mul.rn.f32x2 %0,%1,%2;":"=l"(d):"l"(a),"l"(b)); return d; }
__device__ __forceinline__ ull f2add(ull a, ull b){ ull d; asm("add.rn.f32x2 %0,%1,%2;":"=l"(d):"l"(a),"l"(b)); return d; }
__device__ __forceinline__ ull f2fma(ull a, ull b, ull c){ ull d; asm("fma.rn.f32x2 %0,%1,%2,%3;":"=l"(d):"l"(a),"l"(b),"l"(c)); return d; }

// shared weight buffer layout (floats; all pair-arrays at even offsets)
#define SW_TOK   0     // 42 raw
#define SW_POS   42    // 102 raw
#define SW_LAYER 144   // 4 layers x 102
#define LSZ      102
#define O_LNW    0     // 6  : pairs (lnw[c], lnw[c+3])
#define O_LNB    6     // 6
#define O_Q      12    // 18 : pairs (q1w[r][c]*QS, q2w[r][c]*QS), idx (r*3+c)*2
#define O_K      30    // 18
#define O_V      48    // 18
#define O_OUT    66    // 36 : pairs (ow[pr][c], ow[pr+3][c]), idx (c*3+pr)*2
#define SW_LNF   552   // 6 pairs
#define SW_LNFB  558   // 6 pairs
#define SW_HEAD  564   // 84 : pairs (hw[2i][c], hw[2i+1][c]), idx (i*6+c)*2
#define SW_TOTAL 648

__global__ __launch_bounds__(NTHREADS, 3)
void addtrans_kernel(const int* __restrict__ gidx,
                     const float* __restrict__ tok_emb, const float* __restrict__ pos_enc,
                     const float* __restrict__ ln_w,   const float* __restrict__ ln_b,
                     const float* __restrict__ q1w,    const float* __restrict__ k1w, const float* __restrict__ v1w,
                     const float* __restrict__ q2w,    const float* __restrict__ k2w, const float* __restrict__ v2w,
                     const float* __restrict__ out_w,
                     const float* __restrict__ lnf_w,  const float* __restrict__ lnf_b,
                     const float* __restrict__ head_w,
                     float* __restrict__ out)
{
    __shared__ __align__(16) float skv[NSEQ * SEQ_STRIDE];
    __shared__ __align__(16) float sw[SW_TOTAL];
    __shared__ int sidx[NSEQ * 34];

    const int tid = threadIdx.x;
    const float QSCALE = 0.57735026919f * 1.44269504089f; // 1/sqrt(3) * log2(e)

    // ---------------- stage + pre-pack weights ----------------
    if (tid < 42)  sw[SW_TOK + tid] = tok_emb[tid];
    if (tid < 102) sw[SW_POS + tid] = pos_enc[tid];
    if (tid < 24) {                       // LN pairs, 4 layers x 6
        int l = tid / 6, e = tid % 6, c = e >> 1, h = e & 1;
        sw[SW_LAYER + l*LSZ + O_LNW + e] = ln_w[l*6 + c + h*3];
        sw[SW_LAYER + l*LSZ + O_LNB + e] = ln_b[l*6 + c + h*3];
    }
    if (tid < 72) {                       // Q/K/V pairs, 4 layers x 18
        int l = tid / 18, e = tid % 18, rc = e >> 1, h = e & 1;
        sw[SW_LAYER + l*LSZ + O_Q + e] = (h ? q2w : q1w)[l*9 + rc] * QSCALE;
        sw[SW_LAYER + l*LSZ + O_K + e] = (h ? k2w : k1w)[l*9 + rc];
        sw[SW_LAYER + l*LSZ + O_V + e] = (h ? v2w : v1w)[l*9 + rc];
    }
    if (tid < 144) {                      // out_w pairs, 4 layers x 36
        int l = tid / 36, e = tid % 36, h = e & 1, pr = (e >> 1) % 3, c = e / 6;
        sw[SW_LAYER + l*LSZ + O_OUT + e] = out_w[l*36 + (pr + h*3)*6 + c];
    }
    if (tid < 6) {                        // final LN pairs
        int c = tid >> 1, h = tid & 1;
        sw[SW_LNF  + tid] = lnf_w[c + h*3];
        sw[SW_LNFB + tid] = lnf_b[c + h*3];
    }
    if (tid < 84) {                       // head pairs
        int i = tid / 12, rem = tid % 12, c = rem >> 1, h = rem & 1;
        sw[SW_HEAD + tid] = head_w[(2*i + h)*6 + c];
    }
    if (tid < NSEQ * 34)
        sidx[tid] = gidx[(size_t)blockIdx.x * (NSEQ * 34) + tid];
    __syncthreads();

    // ---------------- thread -> (seq, token) mapping ----------------
    const int w = tid >> 5, lane = tid & 31;
    int s, t, trips;
    bool dead = false;
    if (w < 8) {                 // tokens 4w..4w+3  x  seqs 0..7
        t = 4*w + (lane >> 3);
        s = lane & 7;
        trips = 4*w + 4;
    } else {                     // tail: tokens 32,33 x seqs 0..7 (16 lanes)
        dead = (lane >= 16);
        s = lane & 7;
        t = 32 + ((lane >> 3) & 1);
        trips = 34;
    }
    if (dead) return;

    const int token = sidx[s*34 + t];

    // residual stream, packed (head1|head2): xa=(x0,x3) xb=(x1,x4) xc=(x2,x5)
    ull xa = pk(sw[SW_TOK + token*3 + 0], sw[SW_POS + t*3 + 0]);
    ull xb = pk(sw[SW_TOK + token*3 + 1], sw[SW_POS + t*3 + 1]);
    ull xc = pk(sw[SW_TOK + token*3 + 2], sw[SW_POS + t*3 + 2]);

    const ulonglong2* kb = (const ulonglong2*)&skv[s * SEQ_STRIDE];
    ulonglong2*      kvw = (ulonglong2*)&skv[s * SEQ_STRIDE + t * 12];

    #pragma unroll
    for (int l = 0; l < 4; ++l) {
        const float* LB = &sw[SW_LAYER + l*LSZ];

        // ---- layernorm (packed) ----
        float sl_, sh_;
        unpk(f2add(f2add(xa, xb), xc), sl_, sh_);
        float m = (sl_ + sh_) * (1.0f / 6.0f);
        ull mm = pk(m, m);
        ull neg1 = pk(-1.0f, -1.0f);
        ull da = f2fma(mm, neg1, xa);
        ull db = f2fma(mm, neg1, xb);
        ull dc = f2fma(mm, neg1, xc);
        float vl, vh;
        unpk(f2fma(dc, dc, f2fma(db, db, f2mul(da, da))), vl, vh);
        float r = rsqf((vl + vh) * (1.0f / 6.0f) + 1e-5f);
        ull rr = pk(r, r);
        const ull* LNW = (const ull*)&LB[O_LNW];
        const ull* LNB = (const ull*)&LB[O_LNB];
        ull ha = f2fma(f2mul(da, rr), LNW[0], LNB[0]);
        ull hb = f2fma(f2mul(db, rr), LNW[1], LNB[1]);
        ull hc = f2fma(f2mul(dc, rr), LNW[2], LNB[2]);

        // ---- projections (packed over both heads) ----
        const ull* QW = (const ull*)&LB[O_Q];
        const ull* KW = (const ull*)&LB[O_K];
        const ull* VW = (const ull*)&LB[O_V];
        ull pqx = f2fma(hc, QW[2], f2fma(hb, QW[1], f2mul(ha, QW[0])));
        ull pqy = f2fma(hc, QW[5], f2fma(hb, QW[4], f2mul(ha, QW[3])));
        ull pqz = f2fma(hc, QW[8], f2fma(hb, QW[7], f2mul(ha, QW[6])));
        ull pkx = f2fma(hc, KW[2], f2fma(hb, KW[1], f2mul(ha, KW[0])));
        ull pky = f2fma(hc, KW[5], f2fma(hb, KW[4], f2mul(ha, KW[3])));
        ull pkz = f2fma(hc, KW[8], f2fma(hb, KW[7], f2mul(ha, KW[6])));
        ull pvx = f2fma(hc, VW[2], f2fma(hb, VW[1], f2mul(ha, VW[0])));
        ull pvy = f2fma(hc, VW[5], f2fma(hb, VW[4], f2mul(ha, VW[3])));
        ull pvz = f2fma(hc, VW[8], f2fma(hb, VW[7], f2mul(ha, VW[6])));

        // ---- publish packed k/v: [pkx pky | pkz pvx | pvy pvz] ----
        kvw[0] = make_ulonglong2(pkx, pky);
        kvw[1] = make_ulonglong2(pkz, pvx);
        kvw[2] = make_ulonglong2(pvy, pvz);
        __syncthreads();

        // ---- causal attention, both heads packed ----
        ull pden = 0ull, pox = 0ull, poy = 0ull, poz = 0ull;
        const ulonglong2* kp = kb;
        #pragma unroll 2
        for (int j = 0; j < trips; ++j, kp += 3) {
            ulonglong2 A = kp[0];   // pkx, pky
            ulonglong2 B = kp[1];   // pkz, pvx
            ulonglong2 C = kp[2];   // pvy, pvz
            ull ps = f2fma(pqz, B.x, f2fma(pqy, A.y, f2mul(pqx, A.x)));
            float s1, s2; unpk(ps, s1, s2);
            ull pp = pk(ex2f(s1), ex2f(s2));
            pp = (j <= t) ? pp : 0ull;          // causal mask (2x SEL)
            pden = f2add(pden, pp);
            pox = f2fma(pp, B.y, pox);
            poy = f2fma(pp, C.x, poy);
            poz = f2fma(pp, C.y, poz);
        }
        float d1, d2; unpk(pden, d1, d2);
        ull prd = pk(rcpf(d1), rcpf(d2));
        pox = f2mul(pox, prd);
        poy = f2mul(poy, prd);
        poz = f2mul(poz, prd);

        // ---- output projection + residual (packed over x-pairs) ----
        float o0, o3, o1, o4, o2, o5;
        unpk(pox, o0, o3); unpk(poy, o1, o4); unpk(poz, o2, o5);
        ull b0 = pk(o0, o0), b1 = pk(o1, o1), b2 = pk(o2, o2);
        ull b3 = pk(o3, o3), b4 = pk(o4, o4), b5 = pk(o5, o5);
        const ull* OP = (const ull*)&LB[O_OUT];   // OP[c*3 + pr]
        xa = f2fma(b0, OP[0],  xa); xb = f2fma(b0, OP[1],  xb); xc = f2fma(b0, OP[2],  xc);
        xa = f2fma(b1, OP[3],  xa); xb = f2fma(b1, OP[4],  xb); xc = f2fma(b1, OP[5],  xc);
        xa = f2fma(b2, OP[6],  xa); xb = f2fma(b2, OP[7],  xb); xc = f2fma(b2, OP[8],  xc);
        xa = f2fma(b3, OP[9],  xa); xb = f2fma(b3, OP[10], xb); xc = f2fma(b3, OP[11], xc);
        xa = f2fma(b4, OP[12], xa); xb = f2fma(b4, OP[13], xb); xc = f2fma(b4, OP[14], xc);
        xa = f2fma(b5, OP[15], xa); xb = f2fma(b5, OP[16], xb); xc = f2fma(b5, OP[17], xc);

        __syncthreads();   // kv buffer reused next layer
    }

    // ---------------- final layernorm (packed) ----------------
    float sl_, sh_;
    unpk(f2add(f2add(xa, xb), xc), sl_, sh_);
    float m = (sl_ + sh_) * (1.0f / 6.0f);
    ull mm = pk(m, m);
    ull neg1 = pk(-1.0f, -1.0f);
    ull da = f2fma(mm, neg1, xa);
    ull db = f2fma(mm, neg1, xb);
    ull dc = f2fma(mm, neg1, xc);
    float vl, vh;
    unpk(f2fma(dc, dc, f2fma(db, db, f2mul(da, da))), vl, vh);
    float r = rsqf((vl + vh) * (1.0f / 6.0f) + 1e-5f);
    ull rr = pk(r, r);
    const ull* LNF  = (const ull*)&sw[SW_LNF];
    const ull* LNFB = (const ull*)&sw[SW_LNFB];
    ull ha = f2fma(f2mul(da, rr), LNF[0], LNFB[0]);
    ull hb = f2fma(f2mul(db, rr), LNF[1], LNFB[1]);
    ull hc = f2fma(f2mul(dc, rr), LNF[2], LNFB[2]);

    // h broadcasts for head matvec
    float h0, h3, h1, h4, h2, h5;
    unpk(ha, h0, h3); unpk(hb, h1, h4); unpk(hc, h2, h5);
    ull g0 = pk(h0, h0), g1 = pk(h1, h1), g2 = pk(h2, h2);
    ull g3 = pk(h3, h3), g4 = pk(h4, h4), g5 = pk(h5, h5);

    const ull* HW = (const ull*)&sw[SW_HEAD];   // HW[i*6 + c]
    size_t base = ((size_t)(blockIdx.x * NSEQ + s) * 34 + t) * 14;
    #pragma unroll
    for (int i = 0; i < 7; ++i) {
        ull L = f2mul(g0, HW[i*6 + 0]);
        L = f2fma(g1, HW[i*6 + 1], L);
        L = f2fma(g2, HW[i*6 + 2], L);
        L = f2fma(g3, HW[i*6 + 3], L);
        L = f2fma(g4, HW[i*6 + 4], L);
        L = f2fma(g5, HW[i*6 + 5], L);
        *(ull*)(out + base + 2*i) = L;   // (lg_{2i}, lg_{2i+1})
    }
}

extern "C" void kernel_launch(void* const* d_in, const int* in_sizes, int n_in,
                              void* d_out, int out_size)
{
    (void)in_sizes; (void)n_in; (void)out_size;
    addtrans_kernel<<<2048, NTHREADS>>>(
        (const int*)d_in[0],
        (const float*)d_in[1],  (const float*)d_in[2],
        (const float*)d_in[3],  (const float*)d_in[4],
        (const float*)d_in[5],  (const float*)d_in[6],  (const float*)d_in[7],
        (const float*)d_in[8],  (const float*)d_in[9],  (const float*)d_in[10],
        (const float*)d_in[11],
        (const float*)d_in[12], (const float*)d_in[13],
        (const float*)d_in[14],
        (float*)d_out);
}